// round 2
// baseline (speedup 1.0000x reference)
#include <cuda_runtime.h>
#include <math.h>

#define BB   64
#define SS   128
#define HH   512
#define G3   1536     // 3*H

#define NCTA 128
#define NTHR 256

// scratch (static __device__ arrays are the allowed scratch mechanism)
__device__ float    g_gi[SS * BB * G3];      // [t][b][3H], b_ih included
__device__ float    g_h[2][BB * HH];         // double-buffered hidden state
__device__ unsigned g_count   = 0;           // monotonic across launches
__device__ unsigned g_release = 0;

// ---------------------------------------------------------------------------
// Kernel 1: gi[t][b][n] = emb[tok[b][t]] . W_ih[n] + b_ih[n]
// M=8192 (m=b*128+t), N=1536, K=512. Tiled 128x64, micro 8x4, 256 threads.
// ---------------------------------------------------------------------------
__global__ __launch_bounds__(256) void gi_kernel(
    const int*   __restrict__ tok,
    const float* __restrict__ emb,
    const float* __restrict__ W_ih,
    const float* __restrict__ b_ih)
{
    __shared__ float As[16][128];
    __shared__ float Bs[16][64];

    const int tid = threadIdx.x;
    const int m0  = blockIdx.x * 128;
    const int n0  = blockIdx.y * 64;

    const int mloc  = tid & 127, khalf = tid >> 7;   // A staging: 2 float4 / thread
    const int nloc  = tid & 63,  kq    = tid >> 6;   // B staging: 1 float4 / thread
    const int tmi   = tid >> 4,  tni   = tid & 15;   // compute: 16x16 thread grid

    const float* arow = emb  + (size_t)tok[m0 + mloc] * HH + khalf * 8;
    const float* brow = W_ih + (size_t)(n0 + nloc) * HH + kq * 4;

    float acc[8][4];
    #pragma unroll
    for (int i = 0; i < 8; i++)
        #pragma unroll
        for (int j = 0; j < 4; j++) acc[i][j] = 0.f;

    for (int k0 = 0; k0 < HH; k0 += 16) {
        float4 a0 = *(const float4*)(arow + k0);
        float4 a1 = *(const float4*)(arow + k0 + 4);
        float4 bv = *(const float4*)(brow + k0);
        __syncthreads();   // previous compute done before overwriting tiles
        As[khalf*8+0][mloc] = a0.x; As[khalf*8+1][mloc] = a0.y;
        As[khalf*8+2][mloc] = a0.z; As[khalf*8+3][mloc] = a0.w;
        As[khalf*8+4][mloc] = a1.x; As[khalf*8+5][mloc] = a1.y;
        As[khalf*8+6][mloc] = a1.z; As[khalf*8+7][mloc] = a1.w;
        Bs[kq*4+0][nloc] = bv.x; Bs[kq*4+1][nloc] = bv.y;
        Bs[kq*4+2][nloc] = bv.z; Bs[kq*4+3][nloc] = bv.w;
        __syncthreads();

        #pragma unroll
        for (int k = 0; k < 16; k++) {
            float4 av0 = *(const float4*)&As[k][tmi*8];
            float4 av1 = *(const float4*)&As[k][tmi*8 + 4];
            float4 bv4 = *(const float4*)&Bs[k][tni*4];
            float a[8] = {av0.x,av0.y,av0.z,av0.w,av1.x,av1.y,av1.z,av1.w};
            float b[4] = {bv4.x,bv4.y,bv4.z,bv4.w};
            #pragma unroll
            for (int i = 0; i < 8; i++)
                #pragma unroll
                for (int j = 0; j < 4; j++)
                    acc[i][j] = fmaf(a[i], b[j], acc[i][j]);
        }
    }

    float4 bias = *(const float4*)(b_ih + n0 + tni*4);
    #pragma unroll
    for (int i = 0; i < 8; i++) {
        int m  = m0 + tmi*8 + i;
        int tt = m & 127;
        int bb = m >> 7;
        float4 o;
        o.x = acc[i][0] + bias.x; o.y = acc[i][1] + bias.y;
        o.z = acc[i][2] + bias.z; o.w = acc[i][3] + bias.w;
        *(float4*)(g_gi + ((size_t)tt * BB + bb) * G3 + n0 + tni*4) = o;
    }
}

// ---------------------------------------------------------------------------
// Grid barrier: sense via monotonic generation counter (survives multiple
// launches / graph replays without reset — initial gen read is race-free
// because g_release cannot advance until THIS CTA arrives).
// ---------------------------------------------------------------------------
__device__ __forceinline__ void grid_barrier(unsigned& gen)
{
    __syncthreads();
    if (threadIdx.x == 0) {
        __threadfence();
        unsigned prev = atomicAdd(&g_count, 1u);
        if (prev == gen * NCTA + (NCTA - 1)) {
            atomicExch(&g_release, gen + 1u);
        } else {
            while (*((volatile unsigned*)&g_release) <= gen) { }
        }
    }
    gen++;
    __syncthreads();
}

// ---------------------------------------------------------------------------
// Kernel 2: persistent recurrence + attention.
// 128 CTAs x 256 threads. CTA c owns h-columns [4c, 4c+4); thread = jl*64 + b.
// CTAs 0..63 additionally do attention for batch = CTA id.
// One grid barrier per timestep.
// ---------------------------------------------------------------------------
__global__ __launch_bounds__(NTHR, 1) void decoder_kernel(
    const float* __restrict__ enc_hidden,   // [1,B,H]
    const float* __restrict__ enc_out,      // [B,S,H]
    const float* __restrict__ W_hh,         // [3H,H]
    const float* __restrict__ b_hh,         // [3H]
    float*       __restrict__ out)          // [B,S,2H]
{
    __shared__ float ws[12][HH];     // 12 W_hh rows for this CTA (24 KB)
    __shared__ float hs[64][65];     // staged h chunk (16.6 KB), pad -> no read conflicts
    __shared__ float hb[HH];         // attention: h_t for this batch
    __shared__ float sc[SS];         // attention: scores / probs

    const int tid = threadIdx.x;
    const int cta = blockIdx.x;
    const int jl  = tid >> 6;        // 0..3
    const int bb  = tid & 63;        // 0..63
    const int j0  = cta * 4;
    const int j   = j0 + jl;         // global h-column this thread produces

    // persistent load of W_hh rows: ws[g*4+jj] = W_hh[g*H + j0 + jj]
    for (int idx = tid; idx < 12 * HH; idx += NTHR) {
        int rl = idx >> 9;           // idx / 512
        int k  = idx & 511;
        int g  = rl >> 2, jj = rl & 3;
        ws[rl][k] = W_hh[(size_t)(g * HH + j0 + jj) * HH + k];
    }
    const float bhr = b_hh[j];
    const float bhz = b_hh[HH + j];
    const float bhn = b_hh[2 * HH + j];

    // h[0] = encoder_hidden (cooperative, whole grid)
    for (int idx = cta * NTHR + tid; idx < BB * HH; idx += NCTA * NTHR)
        g_h[0][idx] = enc_hidden[idx];

    unsigned gen = *((volatile unsigned*)&g_release);  // stable at launch
    grid_barrier(gen);

    const int warp = tid >> 5, lane = tid & 31;

    for (int t = 0; t < SS; t++) {
        const int cur = t & 1, nxt = cur ^ 1;
        const float* hcur = g_h[cur];

        // ---- gh = h_{t-1} @ W_hh^T for this CTA's 12 rows ----
        float accr = 0.f, accz = 0.f, accn = 0.f;
        for (int kc = 0; kc < 8; kc++) {
            #pragma unroll
            for (int it = 0; it < 4; it++) {
                int f  = it * 1024 + tid * 4;
                int rb = f >> 6, rk = f & 63;
                float4 v = __ldcg((const float4*)(hcur + rb * HH + kc * 64 + rk));
                hs[rb][rk]   = v.x; hs[rb][rk+1] = v.y;
                hs[rb][rk+2] = v.z; hs[rb][rk+3] = v.w;
            }
            __syncthreads();
            const float* wr = &ws[jl][kc * 64];
            const float* wz = &ws[4 + jl][kc * 64];
            const float* wn = &ws[8 + jl][kc * 64];
            const float* hr = &hs[bb][0];
            #pragma unroll 8
            for (int k = 0; k < 64; k++) {
                float hv = hr[k];
                accr = fmaf(hv, wr[k], accr);
                accz = fmaf(hv, wz[k], accz);
                accn = fmaf(hv, wn[k], accn);
            }
            __syncthreads();
        }

        // ---- GRU gate math -> h_t[b][j] ----
        {
            const float* git = g_gi + ((size_t)t * BB + bb) * G3;
            float ir  = git[j];
            float iz  = git[HH + j];
            float inn = git[2 * HH + j];
            float hprev = __ldcg(hcur + bb * HH + j);
            float r = 1.f / (1.f + expf(-(ir + accr + bhr)));
            float z = 1.f / (1.f + expf(-(iz + accz + bhz)));
            float n = tanhf(inn + r * (accn + bhn));
            g_h[nxt][bb * HH + j] = (1.f - z) * n + z * hprev;
        }

        grid_barrier(gen);   // h_t fully visible grid-wide

        // ---- attention for batch = cta (CTAs 0..63) ----
        if (cta < BB) {
            const float* hn = g_h[nxt] + cta * HH;
            for (int i = tid; i < HH; i += NTHR) hb[i] = __ldcg(hn + i);
            __syncthreads();

            const float* eb = enc_out + (size_t)cta * SS * HH;
            // scores: warp w handles s = w, w+8, ...
            #pragma unroll 4
            for (int si = 0; si < 16; si++) {
                int s = warp + si * 8;
                const float* er = eb + (size_t)s * HH;
                float p = 0.f;
                #pragma unroll 4
                for (int k = lane; k < HH; k += 32) p = fmaf(hb[k], er[k], p);
                #pragma unroll
                for (int o = 16; o; o >>= 1) p += __shfl_down_sync(0xffffffffu, p, o);
                if (lane == 0) sc[s] = p;
            }
            __syncthreads();

            // softmax over 128 (warp 0)
            if (warp == 0) {
                float v0 = sc[lane], v1 = sc[lane+32], v2 = sc[lane+64], v3 = sc[lane+96];
                float m = fmaxf(fmaxf(v0, v1), fmaxf(v2, v3));
                #pragma unroll
                for (int o = 16; o; o >>= 1) m = fmaxf(m, __shfl_xor_sync(0xffffffffu, m, o));
                float e0 = expf(v0 - m), e1 = expf(v1 - m);
                float e2 = expf(v2 - m), e3 = expf(v3 - m);
                float sum = e0 + e1 + e2 + e3;
                #pragma unroll
                for (int o = 16; o; o >>= 1) sum += __shfl_xor_sync(0xffffffffu, sum, o);
                float inv = 1.f / sum;
                sc[lane]      = e0 * inv; sc[lane + 32] = e1 * inv;
                sc[lane + 64] = e2 * inv; sc[lane + 96] = e3 * inv;
            }
            __syncthreads();

            // context[j] = sum_s p[s] * enc[b][s][j]; write y_t = [h_t, ctx]
            float c0 = 0.f, c1 = 0.f;
            const int ja = tid, jb2 = tid + 256;
            #pragma unroll 4
            for (int s = 0; s < SS; s++) {
                float p = sc[s];
                c0 = fmaf(p, eb[(size_t)s * HH + ja],  c0);
                c1 = fmaf(p, eb[(size_t)s * HH + jb2], c1);
            }
            float* orow = out + ((size_t)cta * SS + t) * (2 * HH);
            orow[ja]       = hb[ja];
            orow[jb2]      = hb[jb2];
            orow[HH + ja]  = c0;
            orow[HH + jb2] = c1;
            __syncthreads();   // done with hb/sc before next iteration reuses them
        }
    }
}

// ---------------------------------------------------------------------------
extern "C" void kernel_launch(void* const* d_in, const int* in_sizes, int n_in,
                              void* d_out, int out_size)
{
    const int*   tok  = (const int*)  d_in[0];   // decoder_input [64,128] int32
    const float* ehid = (const float*)d_in[1];   // encoder_hidden [1,64,512]
    const float* eout = (const float*)d_in[2];   // encoder_output [64,128,512]
    const float* emb  = (const float*)d_in[3];   // emb_table [32000,512]
    const float* wih  = (const float*)d_in[4];   // W_ih [1536,512]
    const float* whh  = (const float*)d_in[5];   // W_hh [1536,512]
    const float* bih  = (const float*)d_in[6];   // b_ih [1536]
    const float* bhh  = (const float*)d_in[7];   // b_hh [1536]
    float*       out  = (float*)d_out;           // [64,128,1024]

    gi_kernel<<<dim3(64, 24), 256>>>(tok, emb, wih, bih);
    decoder_kernel<<<NCTA, NTHR>>>(ehid, eout, whh, bhh, out);
}

// round 5
// speedup vs baseline: 2.2521x; 2.2521x over previous
#include <cuda_runtime.h>
#include <cstdint>
#include <math.h>

#define BB   64
#define SS   128
#define HH   512
#define G3   1536
#define NCTA 128
#define NTHR 256

// smem float offsets (decoder)
#define OFF_ES    0        // enc slice  64x512          (32768 floats)
#define OFF_U     32768    // union: h-chunk 64x132 (8448) / partials 768x17 (13056)
#define OFF_HB    45824    // h_t[b]                       (512)
#define OFF_SCOWN 46336    // own 64 scores
#define OFF_SCALL 46400    // all 128 scores / probs
#define OFF_CTX   46528    // peer context partial         (512)
#define SMEM_FLOATS 47040  // 188160 bytes

__device__ __align__(16) float g_gi[SS * BB * G3];
__device__ __align__(16) float g_h[2][BB * HH];
__device__ unsigned g_count   = 0;
__device__ unsigned g_release = 0;

// ---------------------------------------------------------------------------
// Kernel 1: gi[t][b][n] = emb[tok[b][t]] . W_ih[n] + b_ih[n]
// ---------------------------------------------------------------------------
__global__ __launch_bounds__(256) void gi_kernel(
    const int*   __restrict__ tok,
    const float* __restrict__ emb,
    const float* __restrict__ W_ih,
    const float* __restrict__ b_ih)
{
    __shared__ float As[16][128];
    __shared__ float Bs[16][64];

    const int tid = threadIdx.x;
    const int m0  = blockIdx.x * 128;
    const int n0  = blockIdx.y * 64;

    const int mloc  = tid & 127, khalf = tid >> 7;
    const int nloc  = tid & 63,  kq    = tid >> 6;
    const int tmi   = tid >> 4,  tni   = tid & 15;

    const float* arow = emb  + (size_t)tok[m0 + mloc] * HH + khalf * 8;
    const float* brow = W_ih + (size_t)(n0 + nloc) * HH + kq * 4;

    float acc[8][4];
    #pragma unroll
    for (int i = 0; i < 8; i++)
        #pragma unroll
        for (int jx = 0; jx < 4; jx++) acc[i][jx] = 0.f;

    for (int k0 = 0; k0 < HH; k0 += 16) {
        float4 a0 = *(const float4*)(arow + k0);
        float4 a1 = *(const float4*)(arow + k0 + 4);
        float4 bv = *(const float4*)(brow + k0);
        __syncthreads();
        As[khalf*8+0][mloc] = a0.x; As[khalf*8+1][mloc] = a0.y;
        As[khalf*8+2][mloc] = a0.z; As[khalf*8+3][mloc] = a0.w;
        As[khalf*8+4][mloc] = a1.x; As[khalf*8+5][mloc] = a1.y;
        As[khalf*8+6][mloc] = a1.z; As[khalf*8+7][mloc] = a1.w;
        Bs[kq*4+0][nloc] = bv.x; Bs[kq*4+1][nloc] = bv.y;
        Bs[kq*4+2][nloc] = bv.z; Bs[kq*4+3][nloc] = bv.w;
        __syncthreads();

        #pragma unroll
        for (int k = 0; k < 16; k++) {
            float4 av0 = *(const float4*)&As[k][tmi*8];
            float4 av1 = *(const float4*)&As[k][tmi*8 + 4];
            float4 bv4 = *(const float4*)&Bs[k][tni*4];
            float a[8] = {av0.x,av0.y,av0.z,av0.w,av1.x,av1.y,av1.z,av1.w};
            float b[4] = {bv4.x,bv4.y,bv4.z,bv4.w};
            #pragma unroll
            for (int i = 0; i < 8; i++)
                #pragma unroll
                for (int jx = 0; jx < 4; jx++)
                    acc[i][jx] = fmaf(a[i], b[jx], acc[i][jx]);
        }
    }

    float4 bias = *(const float4*)(b_ih + n0 + tni*4);
    #pragma unroll
    for (int i = 0; i < 8; i++) {
        int m  = m0 + tmi*8 + i;
        int tt = m & 127;
        int bb = m >> 7;
        float4 o;
        o.x = acc[i][0] + bias.x; o.y = acc[i][1] + bias.y;
        o.z = acc[i][2] + bias.z; o.w = acc[i][3] + bias.w;
        *(float4*)(g_gi + ((size_t)tt * BB + bb) * G3 + n0 + tni*4) = o;
    }
}

// ---------------------------------------------------------------------------
__device__ __forceinline__ void grid_barrier(unsigned& gen)
{
    __syncthreads();
    if (threadIdx.x == 0) {
        __threadfence();
        unsigned prev = atomicAdd(&g_count, 1u);
        if (prev == gen * NCTA + (NCTA - 1)) {
            atomicExch(&g_release, gen + 1u);
        } else {
            while (*((volatile unsigned*)&g_release) <= gen) { }
        }
    }
    gen++;
    __syncthreads();
}

__device__ __forceinline__ uint32_t smem_u32(const void* p) {
    uint32_t a;
    asm("{ .reg .u64 t; cvta.to.shared.u64 t, %1; cvt.u32.u64 %0, t; }"
        : "=r"(a) : "l"(p));
    return a;
}
__device__ __forceinline__ float dsmem_ld(uint32_t laddr, uint32_t rk) {
    uint32_t r;
    asm("mapa.shared::cluster.u32 %0, %1, %2;" : "=r"(r) : "r"(laddr), "r"(rk));
    float v;
    asm volatile("ld.shared::cluster.f32 %0, [%1];" : "=f"(v) : "r"(r));
    return v;
}
__device__ __forceinline__ void dsmem_st(uint32_t laddr, uint32_t rk, float v) {
    uint32_t r;
    asm("mapa.shared::cluster.u32 %0, %1, %2;" : "=r"(r) : "r"(laddr), "r"(rk));
    asm volatile("st.shared::cluster.f32 [%0], %1;" :: "r"(r), "f"(v));
}
#define CLUSTER_SYNC() do { \
    asm volatile("barrier.cluster.arrive.aligned;" ::: "memory"); \
    asm volatile("barrier.cluster.wait.aligned;"   ::: "memory"); } while (0)

// ---------------------------------------------------------------------------
// Kernel 2: persistent recurrence + attention.
// 128 CTAs (64 clusters of 2) x 256 threads.
// GEMM: CTA owns j in [4*cta, 4*cta+4). Thread = (jl, bgr, ks):
//   jl = tid>>6 (j), bgr = (tid>>4)&3 (16 batches), ks = tid&15 (k-slice).
//   Thread's k elements: k = 128c + ks + 16kk  (c=0..3 chunk, kk=0..7).
//   Weights w[3][32] live in registers for the whole kernel.
// Attention: cluster pair (2b, 2b+1) owns enc_out[b] split s-halves in SMEM.
// ---------------------------------------------------------------------------
__global__ __launch_bounds__(NTHR, 1) __cluster_dims__(2, 1, 1)
void decoder_kernel(
    const float* __restrict__ enc_hidden,
    const float* __restrict__ enc_out,
    const float* __restrict__ W_hh,
    const float* __restrict__ b_hh,
    float*       __restrict__ out)
{
    extern __shared__ float sm[];
    const int tid  = threadIdx.x;
    const int cta  = blockIdx.x;
    const int lane = tid & 31, warp = tid >> 5;
    const int jl   = tid >> 6;
    const int ks   = tid & 15;
    const int bgr  = (tid >> 4) & 3;
    const int j    = cta * 4 + jl;

    uint32_t rank; asm("mov.u32 %0, %%cluster_ctarank;" : "=r"(rank));
    const int half = (int)rank;        // s-half this CTA owns
    const int batt = cta >> 1;         // batch this cluster attends

    // ---- persistent weights in registers: w[g][c*8+kk] = W_hh[g*H+j][128c+ks+16kk]
    float w[3][32];
    #pragma unroll
    for (int g = 0; g < 3; g++) {
        const float* wr = W_hh + ((size_t)(g * HH + j)) * HH;
        #pragma unroll
        for (int c = 0; c < 4; c++)
            #pragma unroll
            for (int kk = 0; kk < 8; kk++)
                w[g][c*8 + kk] = wr[c*128 + ks + 16*kk];
    }
    const float bhr = b_hh[j];
    const float bhz = b_hh[HH + j];
    const float bhn = b_hh[2*HH + j];

    // ---- persistent enc slice: es[64][512] = enc_out[batt][half*64 + s][:]
    {
        const float4* eb  = (const float4*)(enc_out + ((size_t)batt * SS + half*64) * HH);
        float4*       es4 = (float4*)(sm + OFF_ES);
        #pragma unroll
        for (int i = 0; i < 32; i++) es4[tid + 256*i] = eb[tid + 256*i];
    }

    // ---- h0 = encoder_hidden
    for (int idx = cta * NTHR + tid; idx < BB * HH; idx += NCTA * NTHR)
        g_h[0][idx] = enc_hidden[idx];

    unsigned gen = *((volatile unsigned*)&g_release);
    grid_barrier(gen);

    const int b2 = tid & 63;                 // gate-math / output batch

    for (int t = 0; t < SS; t++) {
        const int cur = t & 1, nxt = cur ^ 1;
        const float* hcur = g_h[cur];

        // ================= gh GEMM (weights in regs, h chunked via smem) ====
        float acc[3][16];
        #pragma unroll
        for (int g = 0; g < 3; g++)
            #pragma unroll
            for (int bi = 0; bi < 16; bi++) acc[g][bi] = 0.f;

        #pragma unroll
        for (int c = 0; c < 4; c++) {
            // stage chunk c: h[0..64)[128c..128c+128) -> U (xor-16 row swizzle)
            #pragma unroll
            for (int q = 0; q < 8; q++) {
                int f4  = q * 256 + tid;            // float4 index in chunk
                int row = f4 >> 5;
                int col = (f4 & 31) * 4;
                float4 v = __ldcg((const float4*)(hcur + row*HH + c*128 + col));
                int col2 = col ^ (((row >> 4) & 1) * 16);
                *(float4*)(sm + OFF_U + row*132 + col2) = v;
            }
            __syncthreads();

            #pragma unroll
            for (int bi = 0; bi < 16; bi++) {
                int b = bgr*16 + bi;
                const float* hrow = sm + OFF_U + b*132;
                const int swb = (b >> 4) & 1;
                #pragma unroll
                for (int kk = 0; kk < 8; kk++) {
                    float hv = hrow[ks + 16*(kk ^ swb)];
                    acc[0][bi] = fmaf(hv, w[0][c*8 + kk], acc[0][bi]);
                    acc[1][bi] = fmaf(hv, w[1][c*8 + kk], acc[1][bi]);
                    acc[2][bi] = fmaf(hv, w[2][c*8 + kk], acc[2][bi]);
                }
            }
            __syncthreads();
        }

        // ---- write partials: part[o][ks], o = (jl*64+b)*3+g  (stride 17) ----
        float* part = sm + OFF_U;
        #pragma unroll
        for (int g = 0; g < 3; g++)
            #pragma unroll
            for (int bi = 0; bi < 16; bi++) {
                int o = (jl*64 + bgr*16 + bi) * 3 + g;
                part[o*17 + ks] = acc[g][bi];
            }

        // prefetch gi + hprev for gate math (hide L2 latency under reduction)
        const float* git = g_gi + ((size_t)t * BB + b2) * G3;
        float ir    = git[j];
        float iz    = git[HH + j];
        float inn   = git[2*HH + j];
        float hprev = __ldcg(hcur + b2*HH + j);
        __syncthreads();

        // ---- reduce over 16 k-slices: thread p=tid -> (jl=p>>6, b=p&63) ----
        float s0 = 0.f, s1 = 0.f, s2 = 0.f;
        #pragma unroll
        for (int ksi = 0; ksi < 16; ksi++) {
            s0 += part[(tid*3 + 0)*17 + ksi];
            s1 += part[(tid*3 + 1)*17 + ksi];
            s2 += part[(tid*3 + 2)*17 + ksi];
        }

        // ---- GRU gate math -> h_t[b2][j] ----
        {
            float r = 1.f / (1.f + expf(-(ir + s0 + bhr)));
            float z = 1.f / (1.f + expf(-(iz + s1 + bhz)));
            float n = tanhf(inn + r * (s2 + bhn));
            g_h[nxt][b2*HH + j] = (1.f - z) * n + z * hprev;
        }

        grid_barrier(gen);            // h_t visible grid-wide

        // ================= attention (cluster pair, enc in SMEM) ============
        // load h_t[batt]
        sm[OFF_HB + tid]       = __ldcg(g_h[nxt] + batt*HH + tid);
        sm[OFF_HB + tid + 256] = __ldcg(g_h[nxt] + batt*HH + tid + 256);
        __syncthreads();

        // scores: warp w -> s = w*8+si (own 64-s half)
        float hq[16];
        #pragma unroll
        for (int q = 0; q < 4; q++) {
            float4 v = *(const float4*)(sm + OFF_HB + q*128 + lane*4);
            hq[q*4+0] = v.x; hq[q*4+1] = v.y; hq[q*4+2] = v.z; hq[q*4+3] = v.w;
        }
        #pragma unroll
        for (int si = 0; si < 8; si++) {
            int s_ = warp*8 + si;
            const float* er = sm + OFF_ES + s_*HH;
            float p = 0.f;
            #pragma unroll
            for (int q = 0; q < 4; q++) {
                float4 e = *(const float4*)(er + q*128 + lane*4);
                p = fmaf(hq[q*4+0], e.x, p);
                p = fmaf(hq[q*4+1], e.y, p);
                p = fmaf(hq[q*4+2], e.z, p);
                p = fmaf(hq[q*4+3], e.w, p);
            }
            #pragma unroll
            for (int o = 16; o; o >>= 1) p += __shfl_down_sync(0xffffffffu, p, o);
            if (lane == 0) sm[OFF_SCOWN + s_] = p;
        }
        __syncthreads();
        CLUSTER_SYNC();

        // gather both halves into sm_scall[128]
        if (tid < 64) {
            sm[OFF_SCALL + half*64 + tid] = sm[OFF_SCOWN + tid];
            float pv = dsmem_ld(smem_u32(sm + OFF_SCOWN + tid), rank ^ 1u);
            sm[OFF_SCALL + (half ^ 1)*64 + tid] = pv;
        }
        __syncthreads();

        // softmax over 128 (warp 0, redundant per CTA)
        if (warp == 0) {
            float v0 = sm[OFF_SCALL + lane],      v1 = sm[OFF_SCALL + lane + 32];
            float v2 = sm[OFF_SCALL + lane + 64], v3 = sm[OFF_SCALL + lane + 96];
            float m = fmaxf(fmaxf(v0, v1), fmaxf(v2, v3));
            #pragma unroll
            for (int o = 16; o; o >>= 1) m = fmaxf(m, __shfl_xor_sync(0xffffffffu, m, o));
            float e0 = expf(v0 - m), e1 = expf(v1 - m);
            float e2 = expf(v2 - m), e3 = expf(v3 - m);
            float su = e0 + e1 + e2 + e3;
            #pragma unroll
            for (int o = 16; o; o >>= 1) su += __shfl_xor_sync(0xffffffffu, su, o);
            float inv = 1.f / su;
            sm[OFF_SCALL + lane]      = e0 * inv; sm[OFF_SCALL + lane + 32] = e1 * inv;
            sm[OFF_SCALL + lane + 64] = e2 * inv; sm[OFF_SCALL + lane + 96] = e3 * inv;
        }
        __syncthreads();

        // context partial over own 64 s
        float c0 = 0.f, c1 = 0.f;
        #pragma unroll 8
        for (int si = 0; si < 64; si++) {
            float p = sm[OFF_SCALL + half*64 + si];
            c0 = fmaf(p, sm[OFF_ES + si*HH + tid],       c0);
            c1 = fmaf(p, sm[OFF_ES + si*HH + tid + 256], c1);
        }

        // exchange partial: rank1 -> rank0's ctx buffer
        if (half == 1) {
            dsmem_st(smem_u32(sm + OFF_CTX + tid),       0u, c0);
            dsmem_st(smem_u32(sm + OFF_CTX + tid + 256), 0u, c1);
        }
        CLUSTER_SYNC();

        if (half == 0) {
            float* orow = out + ((size_t)batt * SS + t) * (2*HH);
            orow[tid]            = sm[OFF_HB + tid];
            orow[tid + 256]      = sm[OFF_HB + tid + 256];
            orow[HH + tid]       = c0 + sm[OFF_CTX + tid];
            orow[HH + tid + 256] = c1 + sm[OFF_CTX + tid + 256];
        }
        CLUSTER_SYNC();   // protect sm_hb/scall/ctx before next-step reuse
    }
}

// ---------------------------------------------------------------------------
extern "C" void kernel_launch(void* const* d_in, const int* in_sizes, int n_in,
                              void* d_out, int out_size)
{
    const int*   tok  = (const int*)  d_in[0];
    const float* ehid = (const float*)d_in[1];
    const float* eout = (const float*)d_in[2];
    const float* emb  = (const float*)d_in[3];
    const float* wih  = (const float*)d_in[4];
    const float* whh  = (const float*)d_in[5];
    const float* bih  = (const float*)d_in[6];
    const float* bhh  = (const float*)d_in[7];
    float*       out  = (float*)d_out;

    cudaFuncSetAttribute(decoder_kernel,
                         cudaFuncAttributeMaxDynamicSharedMemorySize,
                         SMEM_FLOATS * sizeof(float));

    gi_kernel<<<dim3(64, 24), 256>>>(tok, emb, wih, bih);
    decoder_kernel<<<NCTA, NTHR, SMEM_FLOATS * sizeof(float)>>>(ehid, eout, whh, bhh, out);
}

// round 9
// speedup vs baseline: 2.4438x; 1.0851x over previous
#include <cuda_runtime.h>
#include <cstdint>
#include <math.h>

#define BB   64
#define SS   128
#define HH   512
#define G3   1536
#define NCTA 128
#define NTHR 512

// smem float offsets (decoder)
#define OFF_ES    0        // enc slice 64x512                  (32768)
#define OFF_WS    32768    // W_hh rows 12x512                  (6144)
#define OFF_U     38912    // union: h-chunk 64x132 / part 768x17 (13056)
#define OFF_HB    51968    // h_t[batt]                         (512)
#define OFF_SCOWN 52480    // own 64 scores                     (64)
#define OFF_SCALL 52544    // all 128 probs                     (128)
#define OFF_CTX   52672    // peer context partial              (512)
#define SMEM_FLOATS 53184  // 212736 bytes

__device__ __align__(16) float g_gi[SS * BB * G3];
__device__ __align__(16) float g_h[2][BB * HH];
__device__ unsigned g_count   = 0;
__device__ unsigned g_release = 0;

// ---------------------------------------------------------------------------
// Kernel 1: gi[t][b][n] = emb[tok[b][t]] . W_ih[n] + b_ih[n]   (unchanged)
// ---------------------------------------------------------------------------
__global__ __launch_bounds__(256) void gi_kernel(
    const int*   __restrict__ tok,
    const float* __restrict__ emb,
    const float* __restrict__ W_ih,
    const float* __restrict__ b_ih)
{
    __shared__ float As[16][128];
    __shared__ float Bs[16][64];

    const int tid = threadIdx.x;
    const int m0  = blockIdx.x * 128;
    const int n0  = blockIdx.y * 64;

    const int mloc  = tid & 127, khalf = tid >> 7;
    const int nloc  = tid & 63,  kq    = tid >> 6;
    const int tmi   = tid >> 4,  tni   = tid & 15;

    const float* arow = emb  + (size_t)tok[m0 + mloc] * HH + khalf * 8;
    const float* brow = W_ih + (size_t)(n0 + nloc) * HH + kq * 4;

    float acc[8][4];
    #pragma unroll
    for (int i = 0; i < 8; i++)
        #pragma unroll
        for (int jx = 0; jx < 4; jx++) acc[i][jx] = 0.f;

    for (int k0 = 0; k0 < HH; k0 += 16) {
        float4 a0 = *(const float4*)(arow + k0);
        float4 a1 = *(const float4*)(arow + k0 + 4);
        float4 bv = *(const float4*)(brow + k0);
        __syncthreads();
        As[khalf*8+0][mloc] = a0.x; As[khalf*8+1][mloc] = a0.y;
        As[khalf*8+2][mloc] = a0.z; As[khalf*8+3][mloc] = a0.w;
        As[khalf*8+4][mloc] = a1.x; As[khalf*8+5][mloc] = a1.y;
        As[khalf*8+6][mloc] = a1.z; As[khalf*8+7][mloc] = a1.w;
        Bs[kq*4+0][nloc] = bv.x; Bs[kq*4+1][nloc] = bv.y;
        Bs[kq*4+2][nloc] = bv.z; Bs[kq*4+3][nloc] = bv.w;
        __syncthreads();

        #pragma unroll
        for (int k = 0; k < 16; k++) {
            float4 av0 = *(const float4*)&As[k][tmi*8];
            float4 av1 = *(const float4*)&As[k][tmi*8 + 4];
            float4 bv4 = *(const float4*)&Bs[k][tni*4];
            float a[8] = {av0.x,av0.y,av0.z,av0.w,av1.x,av1.y,av1.z,av1.w};
            float b[4] = {bv4.x,bv4.y,bv4.z,bv4.w};
            #pragma unroll
            for (int i = 0; i < 8; i++)
                #pragma unroll
                for (int jx = 0; jx < 4; jx++)
                    acc[i][jx] = fmaf(a[i], b[jx], acc[i][jx]);
        }
    }

    float4 bias = *(const float4*)(b_ih + n0 + tni*4);
    #pragma unroll
    for (int i = 0; i < 8; i++) {
        int m  = m0 + tmi*8 + i;
        int tt = m & 127;
        int bb = m >> 7;
        float4 o;
        o.x = acc[i][0] + bias.x; o.y = acc[i][1] + bias.y;
        o.z = acc[i][2] + bias.z; o.w = acc[i][3] + bias.w;
        *(float4*)(g_gi + ((size_t)tt * BB + bb) * G3 + n0 + tni*4) = o;
    }
}

// ---------------------------------------------------------------------------
__device__ __forceinline__ void grid_barrier(unsigned& gen)
{
    __syncthreads();
    if (threadIdx.x == 0) {
        __threadfence();
        unsigned prev = atomicAdd(&g_count, 1u);
        if (prev == gen * NCTA + (NCTA - 1)) {
            atomicExch(&g_release, gen + 1u);
        } else {
            while (*((volatile unsigned*)&g_release) <= gen) { }
        }
    }
    gen++;
    __syncthreads();
}

__device__ __forceinline__ uint32_t smem_u32(const void* p) {
    uint32_t a;
    asm("{ .reg .u64 t; cvta.to.shared.u64 t, %1; cvt.u32.u64 %0, t; }"
        : "=r"(a) : "l"(p));
    return a;
}
__device__ __forceinline__ float dsmem_ld(uint32_t laddr, uint32_t rk) {
    uint32_t r;
    asm("mapa.shared::cluster.u32 %0, %1, %2;" : "=r"(r) : "r"(laddr), "r"(rk));
    float v;
    asm volatile("ld.shared::cluster.f32 %0, [%1];" : "=f"(v) : "r"(r));
    return v;
}
__device__ __forceinline__ void dsmem_st(uint32_t laddr, uint32_t rk, float v) {
    uint32_t r;
    asm("mapa.shared::cluster.u32 %0, %1, %2;" : "=r"(r) : "r"(laddr), "r"(rk));
    asm volatile("st.shared::cluster.f32 [%0], %1;" :: "r"(r), "f"(v));
}
#define CLUSTER_SYNC() do { \
    asm volatile("barrier.cluster.arrive.aligned;" ::: "memory"); \
    asm volatile("barrier.cluster.wait.aligned;"   ::: "memory"); } while (0)

// packed fp32 pair FMA: acc = a*b + acc  (both lanes)
__device__ __forceinline__ void ffma2(uint64_t& acc, uint64_t a, uint64_t b) {
    asm("fma.rn.f32x2 %0, %1, %2, %0;" : "+l"(acc) : "l"(a), "l"(b));
}

// ---------------------------------------------------------------------------
// Kernel 2: persistent recurrence + attention.
// 128 CTAs (64 clusters of 2) x 512 threads.
// GEMM: CTA owns j in [4*cta, 4*cta+4). Thread = (jl, bgr, ks):
//   jl = tid>>7 (j), bgr = (tid>>4)&7 (8 batches), ks = tid&15 (k-pair slice).
//   Thread's k pairs: k = c*128 + 2*ks + 32*m (c chunk 0..3, m 0..3).
//   W_hh rows in SMEM (loaded once); math via packed fma.rn.f32x2.
// ---------------------------------------------------------------------------
__global__ __launch_bounds__(NTHR, 1) __cluster_dims__(2, 1, 1)
void decoder_kernel(
    const float* __restrict__ enc_hidden,
    const float* __restrict__ enc_out,
    const float* __restrict__ W_hh,
    const float* __restrict__ b_hh,
    float*       __restrict__ out)
{
    extern __shared__ float sm[];
    const int tid  = threadIdx.x;
    const int cta  = blockIdx.x;
    const int lane = tid & 31, warp = tid >> 5;
    const int jl   = tid >> 7;           // 0..3
    const int bgr  = (tid >> 4) & 7;     // 0..7  -> batches [8*bgr, 8*bgr+8)
    const int ks   = tid & 15;           // k-pair slice

    uint32_t rank; asm("mov.u32 %0, %%cluster_ctarank;" : "=r"(rank));
    const int half = (int)rank;
    const int batt = cta >> 1;

    // ---- W_hh rows -> SMEM once: ws[g*4+jj][k] = W_hh[g*H + cta*4 + jj][k]
    #pragma unroll
    for (int i = 0; i < 12; i++) {
        int idx = tid + 512 * i;          // 6144 total
        int rl = idx >> 9, k = idx & 511;
        int g = rl >> 2, jj = rl & 3;
        sm[OFF_WS + idx] = W_hh[(size_t)(g * HH + cta * 4 + jj) * HH + k];
    }

    // ---- persistent enc slice: es[64][512] = enc_out[batt][half*64 + s][:]
    {
        const float4* eb  = (const float4*)(enc_out + ((size_t)batt * SS + half*64) * HH);
        float4*       es4 = (float4*)(sm + OFF_ES);
        #pragma unroll
        for (int i = 0; i < 16; i++) es4[tid + 512*i] = eb[tid + 512*i];
    }

    // ---- h0 = encoder_hidden
    for (int idx = cta * NTHR + tid; idx < BB * HH; idx += NCTA * NTHR)
        g_h[0][idx] = enc_hidden[idx];

    unsigned gen = *((volatile unsigned*)&g_release);
    grid_barrier(gen);

    for (int t = 0; t < SS; t++) {
        const int cur = t & 1, nxt = cur ^ 1;
        const float* hcur = g_h[cur];

        // ================= gh GEMM (packed f32x2) ===========================
        uint64_t acc2[3][8];
        #pragma unroll
        for (int g = 0; g < 3; g++)
            #pragma unroll
            for (int bi = 0; bi < 8; bi++) acc2[g][bi] = 0ull;

        #pragma unroll
        for (int c = 0; c < 4; c++) {
            // stage chunk c: h[0..64)[128c..128c+128) -> hs[64][132]
            #pragma unroll
            for (int q = 0; q < 4; q++) {
                int f4  = q * 512 + tid;
                int row = f4 >> 5;
                int col = (f4 & 31) * 4;
                float4 v = __ldcg((const float4*)(hcur + row*HH + c*128 + col));
                *(float4*)(sm + OFF_U + row*132 + col) = v;
            }
            __syncthreads();

            const float* wb  = sm + OFF_WS + jl*512 + c*128 + 2*ks;
            const float* hb0 = sm + OFF_U + (bgr*8)*132 + 2*ks;
            #pragma unroll
            for (int m = 0; m < 4; m++) {
                uint64_t w0 = *(const uint64_t*)(wb + 32*m);
                uint64_t w1 = *(const uint64_t*)(wb + 2048 + 32*m);
                uint64_t w2 = *(const uint64_t*)(wb + 4096 + 32*m);
                #pragma unroll
                for (int bi = 0; bi < 8; bi++) {
                    uint64_t hv = *(const uint64_t*)(hb0 + bi*132 + 32*m);
                    ffma2(acc2[0][bi], hv, w0);
                    ffma2(acc2[1][bi], hv, w1);
                    ffma2(acc2[2][bi], hv, w2);
                }
            }
            __syncthreads();
        }

        // ---- fold lanes, write partials: part[o][ks], o = (jl*64+b)*3+g ----
        float* part = sm + OFF_U;
        #pragma unroll
        for (int g = 0; g < 3; g++)
            #pragma unroll
            for (int bi = 0; bi < 8; bi++) {
                float2 v = *(float2*)&acc2[g][bi];
                int o = (jl*64 + bgr*8 + bi) * 3 + g;
                part[o*17 + ks] = v.x + v.y;
            }

        // prefetch gi + hprev for gate math (threads 0..255 own (j,b) pairs)
        float ir = 0.f, iz = 0.f, inn = 0.f, hprev = 0.f, bhr_ = 0.f, bhz_ = 0.f, bhn_ = 0.f;
        int jr = 0, br = 0;
        if (tid < 256) {
            jr = cta * 4 + (tid >> 6);
            br = tid & 63;
            const float* git = g_gi + ((size_t)t * BB + br) * G3;
            ir    = git[jr];
            iz    = git[HH + jr];
            inn   = git[2*HH + jr];
            hprev = __ldcg(hcur + br*HH + jr);
            bhr_  = b_hh[jr];
            bhz_  = b_hh[HH + jr];
            bhn_  = b_hh[2*HH + jr];
        }
        __syncthreads();

        if (tid < 256) {
            float s0 = 0.f, s1 = 0.f, s2 = 0.f;
            #pragma unroll
            for (int ksi = 0; ksi < 16; ksi++) {
                s0 += part[(tid*3 + 0)*17 + ksi];
                s1 += part[(tid*3 + 1)*17 + ksi];
                s2 += part[(tid*3 + 2)*17 + ksi];
            }
            float r = 1.f / (1.f + expf(-(ir + s0 + bhr_)));
            float z = 1.f / (1.f + expf(-(iz + s1 + bhz_)));
            float n = tanhf(inn + r * (s2 + bhn_));
            g_h[nxt][br*HH + jr] = (1.f - z) * n + z * hprev;
        }

        grid_barrier(gen);            // h_t visible grid-wide

        // ================= attention (cluster pair, enc in SMEM) ============
        sm[OFF_HB + tid] = __ldcg(g_h[nxt] + batt*HH + tid);
        __syncthreads();

        // scores: warp w -> s = w*4+si (own 64-s half)
        float hq[16];
        #pragma unroll
        for (int q = 0; q < 4; q++) {
            float4 v = *(const float4*)(sm + OFF_HB + q*128 + lane*4);
            hq[q*4+0] = v.x; hq[q*4+1] = v.y; hq[q*4+2] = v.z; hq[q*4+3] = v.w;
        }
        #pragma unroll
        for (int si = 0; si < 4; si++) {
            int s_ = warp*4 + si;
            const float* er = sm + OFF_ES + s_*HH;
            float p = 0.f;
            #pragma unroll
            for (int q = 0; q < 4; q++) {
                float4 e = *(const float4*)(er + q*128 + lane*4);
                p = fmaf(hq[q*4+0], e.x, p);
                p = fmaf(hq[q*4+1], e.y, p);
                p = fmaf(hq[q*4+2], e.z, p);
                p = fmaf(hq[q*4+3], e.w, p);
            }
            #pragma unroll
            for (int o = 16; o; o >>= 1) p += __shfl_down_sync(0xffffffffu, p, o);
            if (lane == 0) sm[OFF_SCOWN + s_] = p;
        }
        __syncthreads();
        CLUSTER_SYNC();

        // gather both halves into SCALL[128]
        if (tid < 64) {
            sm[OFF_SCALL + half*64 + tid] = sm[OFF_SCOWN + tid];
            float pv = dsmem_ld(smem_u32(sm + OFF_SCOWN + tid), rank ^ 1u);
            sm[OFF_SCALL + (half ^ 1)*64 + tid] = pv;
        }
        __syncthreads();

        // softmax over 128 (warp 0)
        if (warp == 0) {
            float v0 = sm[OFF_SCALL + lane],      v1 = sm[OFF_SCALL + lane + 32];
            float v2 = sm[OFF_SCALL + lane + 64], v3 = sm[OFF_SCALL + lane + 96];
            float m = fmaxf(fmaxf(v0, v1), fmaxf(v2, v3));
            #pragma unroll
            for (int o = 16; o; o >>= 1) m = fmaxf(m, __shfl_xor_sync(0xffffffffu, m, o));
            float e0 = expf(v0 - m), e1 = expf(v1 - m);
            float e2 = expf(v2 - m), e3 = expf(v3 - m);
            float su = e0 + e1 + e2 + e3;
            #pragma unroll
            for (int o = 16; o; o >>= 1) su += __shfl_xor_sync(0xffffffffu, su, o);
            float inv = 1.f / su;
            sm[OFF_SCALL + lane]      = e0 * inv; sm[OFF_SCALL + lane + 32] = e1 * inv;
            sm[OFF_SCALL + lane + 64] = e2 * inv; sm[OFF_SCALL + lane + 96] = e3 * inv;
        }
        __syncthreads();

        // context partial over own 64 s (thread -> h-column tid)
        float c0 = 0.f;
        #pragma unroll 8
        for (int si = 0; si < 64; si++)
            c0 = fmaf(sm[OFF_SCALL + half*64 + si], sm[OFF_ES + si*HH + tid], c0);

        if (half == 1)
            dsmem_st(smem_u32(sm + OFF_CTX + tid), 0u, c0);
        CLUSTER_SYNC();

        if (half == 0) {
            float* orow = out + ((size_t)batt * SS + t) * (2*HH);
            orow[tid]      = sm[OFF_HB + tid];
            orow[HH + tid] = c0 + sm[OFF_CTX + tid];
        }
    }
}

// ---------------------------------------------------------------------------
extern "C" void kernel_launch(void* const* d_in, const int* in_sizes, int n_in,
                              void* d_out, int out_size)
{
    const int*   tok  = (const int*)  d_in[0];
    const float* ehid = (const float*)d_in[1];
    const float* eout = (const float*)d_in[2];
    const float* emb  = (const float*)d_in[3];
    const float* wih  = (const float*)d_in[4];
    const float* whh  = (const float*)d_in[5];
    const float* bih  = (const float*)d_in[6];
    const float* bhh  = (const float*)d_in[7];
    float*       out  = (float*)d_out;

    cudaFuncSetAttribute(decoder_kernel,
                         cudaFuncAttributeMaxDynamicSharedMemorySize,
                         SMEM_FLOATS * sizeof(float));

    gi_kernel<<<dim3(64, 24), 256>>>(tok, emb, wih, bih);
    decoder_kernel<<<NCTA, NTHR, SMEM_FLOATS * sizeof(float)>>>(ehid, eout, whh, bhh, out);
}